// round 8
// baseline (speedup 1.0000x reference)
#include <cuda_runtime.h>
#include <math.h>

// Problem constants (fixed by the dataset)
#define TT      128
#define TT2     64
#define NCH     1536
#define NC0     10000
#define NCROSS  30000
#define NE      120000
#define DEGCAP  32            // P(Poisson(4) > 32) ~ 1e-22; safe fixed bucket
#define L2E     1.44269504088896f

// ---------------- scratch (static device allocations) ----------------
__device__ float4 g_nb[NCROSS];            // per-node (sbase*, dbase*, qbase, -) [* = log2e-scaled]
__device__ int    g_chanA[NCROSS];
__device__ int    g_chanB[NCROSS];
__device__ float4 g_s4[NCROSS * 32];       // [n][lane] = s ticks 4l..4l+3 (log2e-scaled)
__device__ float4 g_q4[NCROSS * 32];       // [n][lane] = q ticks 4l..4l+3
__device__ int    g_cnt[NCROSS];
__device__ int    g_csr[NCROSS * DEGCAP];  // fixed-capacity incoming-edge buckets
__device__ float  g_coef[12];              // sA sB sT dA dB dT qA qB qT bm (s,d scaled)

// ---------------- init: zero counts + coefficients + node statics ----------------
// W rows (13x4 row-major): 0 sigA, 1 wireA, 2 chanA, 3 zero, 4 planeA,
// 5 sigB, 6 wireB, 7 chanB, 8 zero, 9 planeB, 10 ray_x, 11 ray_y, 12 tick
__global__ void k_init(
    const int* __restrict__ c0, const int* __restrict__ c1, const int* __restrict__ c2,
    const int* __restrict__ g01, const int* __restrict__ g12, const int* __restrict__ g20,
    const float* __restrict__ r01, const float* __restrict__ r12, const float* __restrict__ r20,
    const float* __restrict__ W, const float* __restrict__ bg,
    const float* __restrict__ asrc, const float* __restrict__ adst,
    const float* __restrict__ Wm, const float* __restrict__ bm)
{
    int i = blockIdx.x * blockDim.x + threadIdx.x;
    if (i == 0) {
        float sA = 0, sB = 0, sT = 0, dA = 0, dB = 0, dT = 0, qA = 0, qB = 0, qT = 0;
#pragma unroll
        for (int o = 0; o < 4; o++) {
            float wA = W[o], wB = W[20 + o], wT = W[48 + o];
            sA += wA * asrc[o]; sB += wB * asrc[o]; sT += wT * asrc[o];
            dA += wA * adst[o]; dB += wB * adst[o]; dT += wT * adst[o];
            qA += wA * Wm[o];   qB += wB * Wm[o];   qT += wT * Wm[o];
        }
        g_coef[0] = sA * L2E; g_coef[1] = sB * L2E; g_coef[2] = sT * L2E;
        g_coef[3] = dA * L2E; g_coef[4] = dB * L2E; g_coef[5] = dT * L2E;
        g_coef[6] = qA; g_coef[7] = qB; g_coef[8] = qT;
        g_coef[9] = bm[0];
    }
    if (i >= NCROSS) return;
    g_cnt[i] = 0;

    int p = i / NC0, c = i % NC0;
    const int* g; const float* r; const int* cA; const int* cB; float pA, pB;
    if (p == 0)      { g = g01; r = r01; cA = c0; cB = c1; pA = 0.f; pB = 1.f; }
    else if (p == 1) { g = g12; r = r12; cA = c1; cB = c2; pA = 1.f; pB = 2.f; }
    else             { g = g20; r = r20; cA = c2; cB = c0; pA = 2.f; pB = 0.f; }
    int wA = g[2 * c], wB = g[2 * c + 1];
    int chA = cA[wA], chB = cB[wB];
    float rx = r[2 * c], ry = r[2 * c + 1];
    float fwA = (float)wA, fwB = (float)wB, fcA = (float)chA, fcB = (float)chB;
    float sb = 0.f, db = 0.f, qb = 0.f;
#pragma unroll
    for (int o = 0; o < 4; o++) {
        float base = bg[o]
              + fwA * W[4  + o] + fcA * W[8  + o] + pA * W[16 + o]
              + fwB * W[24 + o] + fcB * W[28 + o] + pB * W[36 + o]
              + rx  * W[40 + o] + ry  * W[44 + o];
        sb += base * asrc[o];
        db += base * adst[o];
        qb += base * Wm[o];
    }
    g_nb[i]    = make_float4(sb * L2E, db * L2E, qb, 0.f);
    g_chanA[i] = chA;
    g_chanB[i] = chB;
}

// ---------------- direct bucket scatter (single pass, 2 edges/thread) ----------------
__global__ void k_scatter(const int* __restrict__ edges) {
    int e0 = (blockIdx.x * blockDim.x + threadIdx.x) * 2;
    if (e0 >= NE) return;
    const int2* src2 = (const int2*)edges;
    const int2* dst2 = (const int2*)(edges + NE);
    int2 s = src2[e0 >> 1];
    int2 d = dst2[e0 >> 1];
    int p0 = atomicAdd(&g_cnt[d.x], 1);
    int p1 = atomicAdd(&g_cnt[d.y], 1);
    if (p0 < DEGCAP) g_csr[d.x * DEGCAP + p0] = s.x;
    if (p1 < DEGCAP) g_csr[d.y * DEGCAP + p1] = s.y;
}

// ---------------- s, q for all (n, t): thread owns 4 consecutive ticks ----------------
__global__ __launch_bounds__(256) void k_sdq(const float* __restrict__ x)
{
    int idx = blockIdx.x * blockDim.x + threadIdx.x;   // [0, NCROSS*32)
    if (idx >= NCROSS * 32) return;
    int n = idx >> 5;
    int l = idx & 31;
    const float4* x4 = (const float4*)x;
    float4 xA = __ldg(&x4[g_chanA[n] * 32 + l]);
    float4 xB = __ldg(&x4[g_chanB[n] * 32 + l]);
    float4 nb = g_nb[n];
    float cSA = g_coef[0], cSB = g_coef[1], cST = g_coef[2];
    float cQA = g_coef[6], cQB = g_coef[7], cQT = g_coef[8];
    float t0 = (float)(4 * l);
    float xa[4] = { xA.x, xA.y, xA.z, xA.w };
    float xb[4] = { xB.x, xB.y, xB.z, xB.w };
    float sv[4], qv[4];
#pragma unroll
    for (int k = 0; k < 4; k++) {
        float tk = t0 + (float)k;
        sv[k] = nb.x + xa[k] * cSA + xb[k] * cSB + tk * cST;
        qv[k] = nb.z + xa[k] * cQA + xb[k] * cQB + tk * cQT;
    }
    g_s4[idx] = make_float4(sv[0], sv[1], sv[2], sv[3]);
    g_q4[idx] = make_float4(qv[0], qv[1], qv[2], qv[3]);
}

// ---------------- GAT aggregation (two-pass softmax) + MLP + sigmoid ----------------
// Warp = one node; lane owns 4 consecutive ticks 4l..4l+3. 8 nodes/block.
// Pass A: max of leaky(s+d) (no exp). Pass B: exp2-sum (den >= 1 guaranteed).
__global__ __launch_bounds__(256) void k_agg(const float* __restrict__ x,
                                             float* __restrict__ out)
{
    __shared__ float s_res[TT * 9];
    int tid  = threadIdx.x;
    int warp = tid >> 5, lane = tid & 31;
    int n0 = blockIdx.x * 8;
    int n  = n0 + warp;
    int deg = g_cnt[n];
    if (deg > DEGCAP) deg = DEGCAP;
    const int* row = g_csr + n * DEGCAP;
    float bmlp = g_coef[9];
    float cDA = g_coef[3], cDB = g_coef[4], cDT = g_coef[5];

    // dv for this lane's 4 ticks (scaled domain)
    const float4* x4 = (const float4*)x;
    float4 nb = g_nb[n];
    float4 xA = x4[g_chanA[n] * 32 + lane];
    float4 xB = x4[g_chanB[n] * 32 + lane];
    float t0 = (float)(4 * lane);
    float xa[4] = { xA.x, xA.y, xA.z, xA.w };
    float xb[4] = { xB.x, xB.y, xB.z, xB.w };
    float dv[4], m[4], den[4], acc[4];
#pragma unroll
    for (int k = 0; k < 4; k++) {
        dv[k]  = nb.y + xa[k] * cDA + xb[k] * cDB + (t0 + (float)k) * cDT;
        m[k]   = -1e30f;
        den[k] = 0.f;
        acc[k] = 0.f;
    }

    // Pass A: max
    int src_next = (deg > 0) ? row[0] : 0;
    for (int j = 0; j < deg; j++) {
        int src = src_next;
        if (j + 1 < deg) src_next = row[j + 1];
        float4 sv = g_s4[src * 32 + lane];
        float ss[4] = { sv.x, sv.y, sv.z, sv.w };
#pragma unroll
        for (int k = 0; k < 4; k++) {
            float e = ss[k] + dv[k];
            e = fmaxf(e, 0.2f * e);      // leaky relu (scaled domain, c>0 ok)
            m[k] = fmaxf(m[k], e);
        }
    }

    // Pass B: exp2 sum (loads hit L1)
    src_next = (deg > 0) ? row[0] : 0;
    for (int j = 0; j < deg; j++) {
        int src = src_next;
        if (j + 1 < deg) src_next = row[j + 1];
        float4 sv = g_s4[src * 32 + lane];
        float4 qv = g_q4[src * 32 + lane];
        float ss[4] = { sv.x, sv.y, sv.z, sv.w };
        float qs[4] = { qv.x, qv.y, qv.z, qv.w };
#pragma unroll
        for (int k = 0; k < 4; k++) {
            float e = ss[k] + dv[k];
            e = fmaxf(e, 0.2f * e);
            float w = exp2f(e - m[k]);   // exp(e_u - m_u) since pre-scaled by log2e
            den[k] += w;
            acc[k] += w * qs[k];
        }
    }

#pragma unroll
    for (int k = 0; k < 4; k++) {
        int t = 4 * lane + k;
        float z = acc[k] / (den[k] + 1e-9f) + bmlp;
        s_res[t * 9 + warp] = 1.f / (1.f + __expf(-z));
    }
    __syncthreads();
#pragma unroll
    for (int p = 0; p < 4; p++) {
        int i = p * 256 + tid;
        int t = i >> 3, c = i & 7;
        out[t * NCROSS + n0 + c] = s_res[t * 9 + c];
    }
}

// ---------------- launch ----------------
extern "C" void kernel_launch(void* const* d_in, const int* in_sizes, int n_in,
                              void* d_out, int out_size)
{
    const float* x    = (const float*)d_in[0];
    const int*   c0   = (const int*)  d_in[1];
    const int*   c1   = (const int*)  d_in[2];
    const int*   c2   = (const int*)  d_in[3];
    const int*   g01  = (const int*)  d_in[4];
    const int*   g12  = (const int*)  d_in[5];
    const int*   g20  = (const int*)  d_in[6];
    const float* r01  = (const float*)d_in[7];
    const float* r12  = (const float*)d_in[8];
    const float* r20  = (const float*)d_in[9];
    const int*   edges= (const int*)  d_in[10];
    const float* Wg   = (const float*)d_in[11];
    const float* asrc = (const float*)d_in[12];
    const float* adst = (const float*)d_in[13];
    const float* bg   = (const float*)d_in[14];
    const float* Wm   = (const float*)d_in[15];
    const float* bm   = (const float*)d_in[16];
    float* out = (float*)d_out;

    const int B = 256;
    k_init<<<(NCROSS + B - 1) / B, B>>>(c0, c1, c2, g01, g12, g20,
                                        r01, r12, r20, Wg, bg, asrc, adst, Wm, bm);
    k_scatter<<<(NE / 2 + B - 1) / B, B>>>(edges);
    k_sdq<<<(NCROSS * 32 + B - 1) / B, B>>>(x);
    k_agg<<<NCROSS / 8, B>>>(x, out);
}